// round 16
// baseline (speedup 1.0000x reference)
#include <cuda_runtime.h>
#include <cuda_bf16.h>

#define BB   16
#define NN   16384
#define RR   1024
#define DD   320
#define BINS 32
#define HH   512
#define EPSV 1e-5f

// ---------------- scratch (device globals; no allocation allowed) ----------------
__device__ float g_S[BB * RR * BINS];   // segment bin sums (2 MB), [br][bin]
__device__ int   g_off[RR + 1];         // segment start offsets (from sorted seg)
__device__ float g_W2p[3 * HH];         // folded W2, SoA [c][h]
__device__ float g_b2p[3];
__device__ int   g_ticket;              // dynamic work counter for mega2

// ---------------- kernel 0: fused setup ----------------
__global__ __launch_bounds__(256) void setup_kernel(const int* __restrict__ seg,
                                                    const float* __restrict__ gamma,
                                                    const float* __restrict__ beta,
                                                    const float* __restrict__ bn_mean,
                                                    const float* __restrict__ bn_var,
                                                    const float* __restrict__ W2,
                                                    const float* __restrict__ b2) {
    int tid = threadIdx.x;
    int idx = blockIdx.x * 256 + tid;

    if (idx == 0) g_ticket = 0;

    // zero the bin-sum accumulator (vectorized: covers all 524288 floats)
    ((float4*)g_S)[idx] = make_float4(0.f, 0.f, 0.f, 0.f);

    // segment offsets via boundary detection on sorted seg
    if (idx < NN) {
        int s = __ldg(&seg[idx]);
        int prev = (idx == 0) ? -1 : __ldg(&seg[idx - 1]);
        for (int r = prev + 1; r <= s; r++) g_off[r] = idx;
        if (idx == NN - 1) {
            for (int r = s + 1; r <= RR; r++) g_off[r] = NN;
        }
    }

    // batchnorm fold (block 511 only)
    if (blockIdx.x == 511) {
        __shared__ float red[8][3];
        float part0 = 0.f, part1 = 0.f, part2 = 0.f;
#pragma unroll
        for (int k = 0; k < 2; k++) {
            int h = k * 256 + tid;
            float s = rsqrtf(__ldg(&bn_var[h]) + EPSV) * __ldg(&gamma[h]);
            float t = __ldg(&beta[h]) - __ldg(&bn_mean[h]) * s;
            float w0 = __ldg(&W2[h * 3 + 0]);
            float w1 = __ldg(&W2[h * 3 + 1]);
            float w2 = __ldg(&W2[h * 3 + 2]);
            g_W2p[0 * HH + h] = w0 * s;
            g_W2p[1 * HH + h] = w1 * s;
            g_W2p[2 * HH + h] = w2 * s;
            part0 += t * w0; part1 += t * w1; part2 += t * w2;
        }
#pragma unroll
        for (int off = 16; off; off >>= 1) {
            part0 += __shfl_xor_sync(0xffffffffu, part0, off);
            part1 += __shfl_xor_sync(0xffffffffu, part1, off);
            part2 += __shfl_xor_sync(0xffffffffu, part2, off);
        }
        int warp = tid >> 5, lane = tid & 31;
        if (lane == 0) { red[warp][0] = part0; red[warp][1] = part1; red[warp][2] = part2; }
        __syncthreads();
        if (tid < 3) {
            float acc = __ldg(&b2[tid]);
#pragma unroll
            for (int w = 0; w < 8; w++) acc += red[w][tid];
            g_b2p[tid] = acc;
        }
    }
}

// ---------------- kernel 1: per-row 10-wide bin sums + segment atomics ----------------
__global__ __launch_bounds__(256) void binsum_kernel(const float* __restrict__ x,
                                                     const int* __restrict__ seg) {
    __shared__ float4 smf4[16 * 80];   // 16 rows x 320 floats = 20KB
    float* sm = (float*)smf4;
    int row0 = blockIdx.x * 16;
    const float4* x4 = (const float4*)x;
#pragma unroll
    for (int k = 0; k < 5; k++) {
        int e = k * 256 + threadIdx.x;          // 0..1279
        int rr = e / 80, c4 = e % 80;
        smf4[rr * 80 + c4] = x4[(size_t)(row0 + rr) * 80 + c4];
    }
    __syncthreads();
#pragma unroll
    for (int t = 0; t < 2; t++) {
        int task = t * 256 + threadIdx.x;       // 0..511 = 16 rows x 32 bins
        int rr = task >> 5, bin = task & 31;
        int row = row0 + rr;
        int b = row >> 14;                      // row / NN
        int i = row & (NN - 1);
        float s = 0.0f;
#pragma unroll
        for (int j = 0; j < 10; j++) s += sm[rr * 320 + bin * 10 + j];
        atomicAdd(&g_S[((b << 10) + seg[i]) * BINS + bin], s);
    }
}

// ---------------- kernel 2: probe — no-op, rotates ncu capture onto mega2 ----------------
__global__ void probe_kernel() {}

// ---------------- kernel 3: persistent mega — dynamic segment ticketing ----------------
// Phase U: Us[16][512] (smem) = pooled[16][32] @ W1[0:32,:]
// Phase B: warp per atom; lane owns 16 h; channel-merged shuffle reduction.
#define MEGA2_SMEM (16 * 129 * 16 + 16 * BINS * 4)

__global__ __launch_bounds__(256) void mega2_kernel(const float* __restrict__ cond,
                                                    const float* __restrict__ W1,
                                                    const float* __restrict__ b1,
                                                    float* __restrict__ out) {
    extern __shared__ float4 dyn[];
    float4* Us4   = dyn;                        // [16][129]
    float*  pooled = (float*)(Us4 + 16 * 129);  // [16][32]
    __shared__ int s_r;

    int tid = threadIdx.x;

    while (true) {
        if (tid == 0) s_r = atomicAdd(&g_ticket, 1);
        __syncthreads();
        int r = s_r;
        if (r >= RR) break;

        int start = __ldg(&g_off[r]);
        int cnt   = __ldg(&g_off[r + 1]) - start;
        if (cnt == 0) { __syncthreads(); continue; }

        // pooled (scaled) into smem — coalesced on bin
        float inv = 1.0f / (10.0f * (float)cnt);
        for (int e = tid; e < BB * BINS; e += 256) {
            int b = e >> 5, bin = e & 31;
            pooled[e] = g_S[(size_t)((b << 10) + r) * BINS + bin] * inv;
        }
        __syncthreads();

        // ---- phase U ----
        {
            int hq = tid & 127, bh = tid >> 7;      // bh in {0,1}
            const float4* W1v = (const float4*)W1;
            float4 acc[8];
#pragma unroll
            for (int k = 0; k < 8; k++) acc[k] = make_float4(0.f, 0.f, 0.f, 0.f);
#pragma unroll 4
            for (int bin = 0; bin < BINS; bin++) {
                float4 w = __ldg(&W1v[bin * 128 + hq]);
#pragma unroll
                for (int k = 0; k < 8; k++) {
                    float p = pooled[(bh * 8 + k) * BINS + bin];
                    acc[k].x = fmaf(p, w.x, acc[k].x);
                    acc[k].y = fmaf(p, w.y, acc[k].y);
                    acc[k].z = fmaf(p, w.z, acc[k].z);
                    acc[k].w = fmaf(p, w.w, acc[k].w);
                }
            }
#pragma unroll
            for (int k = 0; k < 8; k++) Us4[(bh * 8 + k) * 129 + hq] = acc[k];
        }
        __syncthreads();

        // ---- phase B ----
        {
            int warp = tid >> 5, lane = tid & 31;
            const float4* W2p4 = (const float4*)g_W2p;
            const float4* W1c  = (const float4*)(W1 + BINS * HH);
            const float4* b14  = (const float4*)b1;
            float4 p0[4], p1[4], p2[4];
#pragma unroll
            for (int q = 0; q < 4; q++) {
                int hq = q * 32 + lane;
                p0[q] = __ldg(&W2p4[hq]);
                p1[q] = __ldg(&W2p4[128 + hq]);
                p2[q] = __ldg(&W2p4[256 + hq]);
            }
            float bsel = (lane == 0) ? g_b2p[0] : ((lane == 1) ? g_b2p[1] : g_b2p[2]);

            for (int a = warp; a < cnt; a += 8) {
                int i = start + a;
                float c0 = __ldg(&cond[i * 3 + 0]);
                float c1 = __ldg(&cond[i * 3 + 1]);
                float c2 = __ldg(&cond[i * 3 + 2]);
                float4 vr[4];
#pragma unroll
                for (int q = 0; q < 4; q++) {
                    int hq = q * 32 + lane;
                    float4 w0 = __ldg(&W1c[hq]);
                    float4 w1 = __ldg(&W1c[128 + hq]);
                    float4 w2 = __ldg(&W1c[256 + hq]);
                    float4 bv = __ldg(&b14[hq]);
                    vr[q].x = fmaf(c0, w0.x, fmaf(c1, w1.x, fmaf(c2, w2.x, bv.x)));
                    vr[q].y = fmaf(c0, w0.y, fmaf(c1, w1.y, fmaf(c2, w2.y, bv.y)));
                    vr[q].z = fmaf(c0, w0.z, fmaf(c1, w1.z, fmaf(c2, w2.z, bv.z)));
                    vr[q].w = fmaf(c0, w0.w, fmaf(c1, w1.w, fmaf(c2, w2.w, bv.w)));
                }
#pragma unroll 1
                for (int b = 0; b < BB; b++) {
                    const float4* Ub = Us4 + b * 129;
                    float a0 = 0.f, a1 = 0.f, a2 = 0.f;
#pragma unroll
                    for (int q = 0; q < 4; q++) {
                        float4 u = Ub[q * 32 + lane];     // conflict-free LDS.128
                        float z;
                        z = fmaxf(u.x + vr[q].x, 0.f); a0 = fmaf(z, p0[q].x, a0); a1 = fmaf(z, p1[q].x, a1); a2 = fmaf(z, p2[q].x, a2);
                        z = fmaxf(u.y + vr[q].y, 0.f); a0 = fmaf(z, p0[q].y, a0); a1 = fmaf(z, p1[q].y, a1); a2 = fmaf(z, p2[q].y, a2);
                        z = fmaxf(u.z + vr[q].z, 0.f); a0 = fmaf(z, p0[q].z, a0); a1 = fmaf(z, p1[q].z, a1); a2 = fmaf(z, p2[q].z, a2);
                        z = fmaxf(u.w + vr[q].w, 0.f); a0 = fmaf(z, p0[q].w, a0); a1 = fmaf(z, p1[q].w, a1); a2 = fmaf(z, p2[q].w, a2);
                    }
                    // channel-merged reduction: lane0 -> a0 sum, lane1 -> a1, lane2 -> a2
                    float send1 = (lane & 1) ? a0 : a1;
                    float recv1 = __shfl_xor_sync(0xffffffffu, send1, 1);
                    float m01   = ((lane & 1) ? a1 : a0) + recv1;
                    a2 += __shfl_xor_sync(0xffffffffu, a2, 1);
                    float send2 = (lane & 2) ? m01 : a2;
                    float recv2 = __shfl_xor_sync(0xffffffffu, send2, 2);
                    float m     = ((lane & 2) ? a2 : m01) + recv2;
                    m += __shfl_xor_sync(0xffffffffu, m, 4);
                    m += __shfl_xor_sync(0xffffffffu, m, 8);
                    m += __shfl_xor_sync(0xffffffffu, m, 16);
                    if (lane < 3) out[((size_t)b * NN + i) * 3 + lane] = m + bsel;
                }
            }
        }
        __syncthreads();   // protect smem before next ticket's writes
    }
}

// ---------------- launch ----------------
extern "C" void kernel_launch(void* const* d_in, const int* in_sizes, int n_in,
                              void* d_out, int out_size) {
    const float* x       = (const float*)d_in[0];
    const float* cond    = (const float*)d_in[1];
    const int*   seg     = (const int*)  d_in[2];
    const float* W1      = (const float*)d_in[3];
    const float* b1      = (const float*)d_in[4];
    const float* gamma   = (const float*)d_in[5];
    const float* beta    = (const float*)d_in[6];
    const float* bn_mean = (const float*)d_in[7];
    const float* bn_var  = (const float*)d_in[8];
    const float* W2      = (const float*)d_in[9];
    const float* b2      = (const float*)d_in[10];
    float* out = (float*)d_out;

    cudaFuncSetAttribute(mega2_kernel, cudaFuncAttributeMaxDynamicSharedMemorySize, MEGA2_SMEM);

    setup_kernel<<<512, 256>>>(seg, gamma, beta, bn_mean, bn_var, W2, b2);
    binsum_kernel<<<(BB * NN) / 16, 256>>>(x, seg);
    probe_kernel<<<1, 32>>>();   // rotates ncu's 4th-launch capture onto mega2
    mega2_kernel<<<592, 256, MEGA2_SMEM>>>(cond, W1, b1, out);
}

// round 17
// speedup vs baseline: 1.1104x; 1.1104x over previous
#include <cuda_runtime.h>
#include <cuda_bf16.h>

#define BB   16
#define NN   16384
#define RR   1024
#define DD   320
#define BINS 32
#define HH   512
#define EPSV 1e-5f

// ---------------- scratch (device globals; no allocation allowed) ----------------
__device__ float g_S[BB * RR * BINS];   // segment bin sums (2 MB), [br][bin]
__device__ int   g_off[RR + 1];         // segment start offsets (from sorted seg)
__device__ float g_W2p[3 * HH];         // folded W2, SoA [c][h]
__device__ float g_b2p[3];
__device__ int   g_ticket;              // dynamic work counter for mega2

// ---------------- kernel 0: fused setup ----------------
__global__ __launch_bounds__(256) void setup_kernel(const int* __restrict__ seg,
                                                    const float* __restrict__ gamma,
                                                    const float* __restrict__ beta,
                                                    const float* __restrict__ bn_mean,
                                                    const float* __restrict__ bn_var,
                                                    const float* __restrict__ W2,
                                                    const float* __restrict__ b2) {
    int tid = threadIdx.x;
    int idx = blockIdx.x * 256 + tid;

    if (idx == 0) g_ticket = 0;

    // zero the bin-sum accumulator (vectorized: covers all 524288 floats)
    ((float4*)g_S)[idx] = make_float4(0.f, 0.f, 0.f, 0.f);

    // segment offsets via boundary detection on sorted seg
    if (idx < NN) {
        int s = __ldg(&seg[idx]);
        int prev = (idx == 0) ? -1 : __ldg(&seg[idx - 1]);
        for (int r = prev + 1; r <= s; r++) g_off[r] = idx;
        if (idx == NN - 1) {
            for (int r = s + 1; r <= RR; r++) g_off[r] = NN;
        }
    }

    // batchnorm fold (block 511 only)
    if (blockIdx.x == 511) {
        __shared__ float red[8][3];
        float part0 = 0.f, part1 = 0.f, part2 = 0.f;
#pragma unroll
        for (int k = 0; k < 2; k++) {
            int h = k * 256 + tid;
            float s = rsqrtf(__ldg(&bn_var[h]) + EPSV) * __ldg(&gamma[h]);
            float t = __ldg(&beta[h]) - __ldg(&bn_mean[h]) * s;
            float w0 = __ldg(&W2[h * 3 + 0]);
            float w1 = __ldg(&W2[h * 3 + 1]);
            float w2 = __ldg(&W2[h * 3 + 2]);
            g_W2p[0 * HH + h] = w0 * s;
            g_W2p[1 * HH + h] = w1 * s;
            g_W2p[2 * HH + h] = w2 * s;
            part0 += t * w0; part1 += t * w1; part2 += t * w2;
        }
#pragma unroll
        for (int off = 16; off; off >>= 1) {
            part0 += __shfl_xor_sync(0xffffffffu, part0, off);
            part1 += __shfl_xor_sync(0xffffffffu, part1, off);
            part2 += __shfl_xor_sync(0xffffffffu, part2, off);
        }
        int warp = tid >> 5, lane = tid & 31;
        if (lane == 0) { red[warp][0] = part0; red[warp][1] = part1; red[warp][2] = part2; }
        __syncthreads();
        if (tid < 3) {
            float acc = __ldg(&b2[tid]);
#pragma unroll
            for (int w = 0; w < 8; w++) acc += red[w][tid];
            g_b2p[tid] = acc;
        }
    }
}

// ---------------- kernel 1: per-row 10-wide bin sums + segment atomics ----------------
__global__ __launch_bounds__(256) void binsum_kernel(const float* __restrict__ x,
                                                     const int* __restrict__ seg) {
    __shared__ float4 smf4[16 * 80];   // 16 rows x 320 floats = 20KB
    float* sm = (float*)smf4;
    int row0 = blockIdx.x * 16;
    const float4* x4 = (const float4*)x;
#pragma unroll
    for (int k = 0; k < 5; k++) {
        int e = k * 256 + threadIdx.x;          // 0..1279
        int rr = e / 80, c4 = e % 80;
        smf4[rr * 80 + c4] = x4[(size_t)(row0 + rr) * 80 + c4];
    }
    __syncthreads();
#pragma unroll
    for (int t = 0; t < 2; t++) {
        int task = t * 256 + threadIdx.x;       // 0..511 = 16 rows x 32 bins
        int rr = task >> 5, bin = task & 31;
        int row = row0 + rr;
        int b = row >> 14;                      // row / NN
        int i = row & (NN - 1);
        float s = 0.0f;
#pragma unroll
        for (int j = 0; j < 10; j++) s += sm[rr * 320 + bin * 10 + j];
        atomicAdd(&g_S[((b << 10) + seg[i]) * BINS + bin], s);
    }
}

// ---------------- kernel 2: probe — no-op, rotates ncu capture onto mega2 ----------------
__global__ void probe_kernel() {}

// ---------------- kernel 3: persistent mega — dynamic ticketing, b-loop unrolled x2 ----------------
#define MEGA2_SMEM (16 * 129 * 16 + 16 * BINS * 4)

__global__ __launch_bounds__(256) void mega2_kernel(const float* __restrict__ cond,
                                                    const float* __restrict__ W1,
                                                    const float* __restrict__ b1,
                                                    float* __restrict__ out) {
    extern __shared__ float4 dyn[];
    float4* Us4   = dyn;                        // [16][129]
    float*  pooled = (float*)(Us4 + 16 * 129);  // [16][32]
    __shared__ int s_r;

    int tid = threadIdx.x;

    while (true) {
        if (tid == 0) s_r = atomicAdd(&g_ticket, 1);
        __syncthreads();
        int r = s_r;
        if (r >= RR) break;

        int start = __ldg(&g_off[r]);
        int cnt   = __ldg(&g_off[r + 1]) - start;
        if (cnt == 0) { __syncthreads(); continue; }

        // pooled (scaled) into smem — coalesced on bin
        float inv = 1.0f / (10.0f * (float)cnt);
        for (int e = tid; e < BB * BINS; e += 256) {
            int b = e >> 5, bin = e & 31;
            pooled[e] = g_S[(size_t)((b << 10) + r) * BINS + bin] * inv;
        }
        __syncthreads();

        // ---- phase U ----
        {
            int hq = tid & 127, bh = tid >> 7;      // bh in {0,1}
            const float4* W1v = (const float4*)W1;
            float4 acc[8];
#pragma unroll
            for (int k = 0; k < 8; k++) acc[k] = make_float4(0.f, 0.f, 0.f, 0.f);
#pragma unroll 4
            for (int bin = 0; bin < BINS; bin++) {
                float4 w = __ldg(&W1v[bin * 128 + hq]);
#pragma unroll
                for (int k = 0; k < 8; k++) {
                    float p = pooled[(bh * 8 + k) * BINS + bin];
                    acc[k].x = fmaf(p, w.x, acc[k].x);
                    acc[k].y = fmaf(p, w.y, acc[k].y);
                    acc[k].z = fmaf(p, w.z, acc[k].z);
                    acc[k].w = fmaf(p, w.w, acc[k].w);
                }
            }
#pragma unroll
            for (int k = 0; k < 8; k++) Us4[(bh * 8 + k) * 129 + hq] = acc[k];
        }
        __syncthreads();

        // ---- phase B ----
        {
            int warp = tid >> 5, lane = tid & 31;
            const float4* W2p4 = (const float4*)g_W2p;
            const float4* W1c  = (const float4*)(W1 + BINS * HH);
            const float4* b14  = (const float4*)b1;
            float4 p0[4], p1[4], p2[4];
#pragma unroll
            for (int q = 0; q < 4; q++) {
                int hq = q * 32 + lane;
                p0[q] = __ldg(&W2p4[hq]);
                p1[q] = __ldg(&W2p4[128 + hq]);
                p2[q] = __ldg(&W2p4[256 + hq]);
            }
            float bsel = (lane == 0) ? g_b2p[0] : ((lane == 1) ? g_b2p[1] : g_b2p[2]);

            for (int a = warp; a < cnt; a += 8) {
                int i = start + a;
                float c0 = __ldg(&cond[i * 3 + 0]);
                float c1 = __ldg(&cond[i * 3 + 1]);
                float c2 = __ldg(&cond[i * 3 + 2]);
                float4 vr[4];
#pragma unroll
                for (int q = 0; q < 4; q++) {
                    int hq = q * 32 + lane;
                    float4 w0 = __ldg(&W1c[hq]);
                    float4 w1 = __ldg(&W1c[128 + hq]);
                    float4 w2 = __ldg(&W1c[256 + hq]);
                    float4 bv = __ldg(&b14[hq]);
                    vr[q].x = fmaf(c0, w0.x, fmaf(c1, w1.x, fmaf(c2, w2.x, bv.x)));
                    vr[q].y = fmaf(c0, w0.y, fmaf(c1, w1.y, fmaf(c2, w2.y, bv.y)));
                    vr[q].z = fmaf(c0, w0.z, fmaf(c1, w1.z, fmaf(c2, w2.z, bv.z)));
                    vr[q].w = fmaf(c0, w0.w, fmaf(c1, w1.w, fmaf(c2, w2.w, bv.w)));
                }
                size_t obase = (size_t)i * 3 + lane;
#pragma unroll 1
                for (int b = 0; b < BB; b += 2) {   // two independent chains in flight
                    const float4* Ub0 = Us4 + b * 129;
                    const float4* Ub1 = Us4 + (b + 1) * 129;
                    float a0 = 0.f, a1 = 0.f, a2 = 0.f;
                    float d0 = 0.f, d1 = 0.f, d2 = 0.f;
#pragma unroll
                    for (int q = 0; q < 4; q++) {
                        float4 u0 = Ub0[q * 32 + lane];   // conflict-free LDS.128
                        float4 u1 = Ub1[q * 32 + lane];
                        float z;
                        z = fmaxf(u0.x + vr[q].x, 0.f); a0 = fmaf(z, p0[q].x, a0); a1 = fmaf(z, p1[q].x, a1); a2 = fmaf(z, p2[q].x, a2);
                        z = fmaxf(u1.x + vr[q].x, 0.f); d0 = fmaf(z, p0[q].x, d0); d1 = fmaf(z, p1[q].x, d1); d2 = fmaf(z, p2[q].x, d2);
                        z = fmaxf(u0.y + vr[q].y, 0.f); a0 = fmaf(z, p0[q].y, a0); a1 = fmaf(z, p1[q].y, a1); a2 = fmaf(z, p2[q].y, a2);
                        z = fmaxf(u1.y + vr[q].y, 0.f); d0 = fmaf(z, p0[q].y, d0); d1 = fmaf(z, p1[q].y, d1); d2 = fmaf(z, p2[q].y, d2);
                        z = fmaxf(u0.z + vr[q].z, 0.f); a0 = fmaf(z, p0[q].z, a0); a1 = fmaf(z, p1[q].z, a1); a2 = fmaf(z, p2[q].z, a2);
                        z = fmaxf(u1.z + vr[q].z, 0.f); d0 = fmaf(z, p0[q].z, d0); d1 = fmaf(z, p1[q].z, d1); d2 = fmaf(z, p2[q].z, d2);
                        z = fmaxf(u0.w + vr[q].w, 0.f); a0 = fmaf(z, p0[q].w, a0); a1 = fmaf(z, p1[q].w, a1); a2 = fmaf(z, p2[q].w, a2);
                        z = fmaxf(u1.w + vr[q].w, 0.f); d0 = fmaf(z, p0[q].w, d0); d1 = fmaf(z, p1[q].w, d1); d2 = fmaf(z, p2[q].w, d2);
                    }
                    // channel-merged reductions (two independent trees)
                    float sA1 = (lane & 1) ? a0 : a1;
                    float rA1 = __shfl_xor_sync(0xffffffffu, sA1, 1);
                    float mA  = ((lane & 1) ? a1 : a0) + rA1;
                    a2 += __shfl_xor_sync(0xffffffffu, a2, 1);
                    float sB1 = (lane & 1) ? d0 : d1;
                    float rB1 = __shfl_xor_sync(0xffffffffu, sB1, 1);
                    float mB  = ((lane & 1) ? d1 : d0) + rB1;
                    d2 += __shfl_xor_sync(0xffffffffu, d2, 1);
                    float sA2 = (lane & 2) ? mA : a2;
                    float rA2 = __shfl_xor_sync(0xffffffffu, sA2, 2);
                    float fA  = ((lane & 2) ? a2 : mA) + rA2;
                    float sB2 = (lane & 2) ? mB : d2;
                    float rB2 = __shfl_xor_sync(0xffffffffu, sB2, 2);
                    float fB  = ((lane & 2) ? d2 : mB) + rB2;
                    fA += __shfl_xor_sync(0xffffffffu, fA, 4);
                    fB += __shfl_xor_sync(0xffffffffu, fB, 4);
                    fA += __shfl_xor_sync(0xffffffffu, fA, 8);
                    fB += __shfl_xor_sync(0xffffffffu, fB, 8);
                    fA += __shfl_xor_sync(0xffffffffu, fA, 16);
                    fB += __shfl_xor_sync(0xffffffffu, fB, 16);
                    if (lane < 3) {
                        out[(size_t)b * (NN * 3) + obase]       = fA + bsel;
                        out[(size_t)(b + 1) * (NN * 3) + obase] = fB + bsel;
                    }
                }
            }
        }
        __syncthreads();   // protect smem before next ticket's writes
    }
}

// ---------------- launch ----------------
extern "C" void kernel_launch(void* const* d_in, const int* in_sizes, int n_in,
                              void* d_out, int out_size) {
    const float* x       = (const float*)d_in[0];
    const float* cond    = (const float*)d_in[1];
    const int*   seg     = (const int*)  d_in[2];
    const float* W1      = (const float*)d_in[3];
    const float* b1      = (const float*)d_in[4];
    const float* gamma   = (const float*)d_in[5];
    const float* beta    = (const float*)d_in[6];
    const float* bn_mean = (const float*)d_in[7];
    const float* bn_var  = (const float*)d_in[8];
    const float* W2      = (const float*)d_in[9];
    const float* b2      = (const float*)d_in[10];
    float* out = (float*)d_out;

    cudaFuncSetAttribute(mega2_kernel, cudaFuncAttributeMaxDynamicSharedMemorySize, MEGA2_SMEM);

    setup_kernel<<<512, 256>>>(seg, gamma, beta, bn_mean, bn_var, W2, b2);
    binsum_kernel<<<(BB * NN) / 16, 256>>>(x, seg);
    probe_kernel<<<1, 32>>>();   // rotates ncu's 4th-launch capture onto mega2
    mega2_kernel<<<296, 256, MEGA2_SMEM>>>(cond, W1, b1, out);
}